// round 14
// baseline (speedup 1.0000x reference)
#include <cuda_runtime.h>
#include <cstdint>
#include <mma.h>
#include <math.h>
#include <cuda_bf16.h>
#include <cuda_fp16.h>

using namespace nvcuda;

#define DM   1024
#define NB   4
#define SQ   4096

// Scratch (device globals: the sanctioned alloc-free workaround)
__device__ __nv_bfloat16 g_xh[(size_t)NB * SQ * DM];
__device__ __nv_bfloat16 g_xl[(size_t)NB * SQ * DM];
__device__ __nv_bfloat16 g_wh[3][(size_t)DM * DM];
__device__ __nv_bfloat16 g_wl[3][(size_t)DM * DM];
__device__ __half g_qh[(size_t)NB * SQ * DM];
__device__ __half g_kh[(size_t)NB * SQ * DM];
__device__ __half g_vh[(size_t)NB * SQ * DM];
__device__ __half g_p [(size_t)NB * SQ * SQ];          // unnormalized exp(scores)
__device__ float  g_partial[(size_t)NB * SQ * 64];     // per-(row, score-tile) sums
__device__ float  g_rowsum[(size_t)NB * SQ];

__device__ __forceinline__ void cp_async16(void* dst_smem, const void* src_gmem)
{
    uint32_t d = (uint32_t)__cvta_generic_to_shared(dst_smem);
    asm volatile("cp.async.cg.shared.global [%0], [%1], 16;\n" :: "r"(d), "l"(src_gmem));
}
__device__ __forceinline__ void cp_commit() { asm volatile("cp.async.commit_group;\n" ::); }
__device__ __forceinline__ void cp_wait0()  { asm volatile("cp.async.wait_group 0;\n" ::); }
__device__ __forceinline__ void cp_wait1()  { asm volatile("cp.async.wait_group 1;\n" ::); }

// ===========================================================================
// Elementwise split: fp32 -> bf16 hi + bf16 lo.
// ===========================================================================
__global__ void __launch_bounds__(256) split_bf16(
    const float* __restrict__ in, __nv_bfloat16* __restrict__ h,
    __nv_bfloat16* __restrict__ l, int n)
{
    int idx = (blockIdx.x * 256 + threadIdx.x) * 4;
    if (idx >= n) return;
    float4 v = *(const float4*)&in[idx];
    __nv_bfloat16 h0 = __float2bfloat16_rn(v.x);
    __nv_bfloat16 h1 = __float2bfloat16_rn(v.y);
    __nv_bfloat16 h2 = __float2bfloat16_rn(v.z);
    __nv_bfloat16 h3 = __float2bfloat16_rn(v.w);
    __nv_bfloat16 l0 = __float2bfloat16_rn(v.x - __bfloat162float(h0));
    __nv_bfloat16 l1 = __float2bfloat16_rn(v.y - __bfloat162float(h1));
    __nv_bfloat16 l2 = __float2bfloat16_rn(v.z - __bfloat162float(h2));
    __nv_bfloat16 l3 = __float2bfloat16_rn(v.w - __bfloat162float(h3));
    ushort4 hv = { __bfloat16_as_ushort(h0), __bfloat16_as_ushort(h1),
                   __bfloat16_as_ushort(h2), __bfloat16_as_ushort(h3) };
    ushort4 lv = { __bfloat16_as_ushort(l0), __bfloat16_as_ushort(l1),
                   __bfloat16_as_ushort(l2), __bfloat16_as_ushort(l3) };
    *(ushort4*)&h[idx] = hv;
    *(ushort4*)&l[idx] = lv;
}

// ===========================================================================
// QKV: C(M,N) = (Ah+Al)(M,K) x (Bh+Bl)(N,K)^T, bf16 3-term, fp32 accum.
// Epilogue: stage in smem, write fp16 directly.
// ===========================================================================
__global__ void __launch_bounds__(256, 2) gemm_qkv_bf16(
    const __nv_bfloat16* __restrict__ Ah, const __nv_bfloat16* __restrict__ Al,
    const __nv_bfloat16* __restrict__ Bh, const __nv_bfloat16* __restrict__ Bl,
    __half* __restrict__ C, int N, int K)
{
    constexpr int BM = 128, BN = 128, BK = 32, LD = BK + 16;
    constexpr int LDS = 132;
    extern __shared__ __align__(16) char smraw[];
    __nv_bfloat16* sAh = (__nv_bfloat16*)smraw;
    __nv_bfloat16* sAl = sAh + 2 * BM * LD;
    __nv_bfloat16* sBh = sAl + 2 * BM * LD;
    __nv_bfloat16* sBl = sBh + 2 * BN * LD;

    const int tm   = blockIdx.y * BM;
    const int tn   = blockIdx.x * BN;
    const int tid  = threadIdx.x;
    const int warp = tid >> 5;
    const int wm   = (warp >> 1) * 32;
    const int wn   = (warp & 1) * 64;

    wmma::fragment<wmma::accumulator, 16, 16, 16, float> acc[2][4];
#pragma unroll
    for (int i = 0; i < 2; i++)
#pragma unroll
        for (int j = 0; j < 4; j++) wmma::fill_fragment(acc[i][j], 0.0f);

    const int lr = tid >> 1;
    const int lc = (tid & 1) * 16;

    auto load_tile = [&](int buf, int kk) {
        long ga = (long)(tm + lr) * K + kk + lc;
        long gb = (long)(tn + lr) * K + kk + lc;
        int  sa = (buf * BM + lr) * LD + lc;
        int  sb = (buf * BN + lr) * LD + lc;
        cp_async16(&sAh[sa],     &Ah[ga]);
        cp_async16(&sAh[sa + 8], &Ah[ga + 8]);
        cp_async16(&sAl[sa],     &Al[ga]);
        cp_async16(&sAl[sa + 8], &Al[ga + 8]);
        cp_async16(&sBh[sb],     &Bh[gb]);
        cp_async16(&sBh[sb + 8], &Bh[gb + 8]);
        cp_async16(&sBl[sb],     &Bl[gb]);
        cp_async16(&sBl[sb + 8], &Bl[gb + 8]);
        cp_commit();
    };

    load_tile(0, 0);
    int buf = 0;
    for (int kk = 0; kk < K; kk += BK) {
        const bool has_next = (kk + BK) < K;
        if (has_next) {
            load_tile(buf ^ 1, kk + BK);
            cp_wait1();
        } else {
            cp_wait0();
        }
        __syncthreads();

#pragma unroll
        for (int ks = 0; ks < BK; ks += 16) {
            wmma::fragment<wmma::matrix_a, 16, 16, 16, __nv_bfloat16, wmma::row_major> ah[2], al[2];
            wmma::fragment<wmma::matrix_b, 16, 16, 16, __nv_bfloat16, wmma::col_major> bh[4], bl[4];
#pragma unroll
            for (int i = 0; i < 2; i++) {
                wmma::load_matrix_sync(ah[i], &sAh[(buf * BM + wm + i * 16) * LD + ks], LD);
                wmma::load_matrix_sync(al[i], &sAl[(buf * BM + wm + i * 16) * LD + ks], LD);
            }
#pragma unroll
            for (int j = 0; j < 4; j++) {
                wmma::load_matrix_sync(bh[j], &sBh[(buf * BN + wn + j * 16) * LD + ks], LD);
                wmma::load_matrix_sync(bl[j], &sBl[(buf * BN + wn + j * 16) * LD + ks], LD);
            }
#pragma unroll
            for (int i = 0; i < 2; i++)
#pragma unroll
                for (int j = 0; j < 4; j++) {
                    wmma::mma_sync(acc[i][j], ah[i], bl[j], acc[i][j]);
                    wmma::mma_sync(acc[i][j], al[i], bh[j], acc[i][j]);
                    wmma::mma_sync(acc[i][j], ah[i], bh[j], acc[i][j]);
                }
        }
        __syncthreads();
        buf ^= 1;
    }

    // Epilogue: stage fp32 acc in smem, convert to fp16, write.
    float* st = (float*)smraw;      // [128][LDS]
    __syncthreads();
#pragma unroll
    for (int i = 0; i < 2; i++)
#pragma unroll
        for (int j = 0; j < 4; j++)
            wmma::store_matrix_sync(&st[(wm + i * 16) * LDS + wn + j * 16],
                                    acc[i][j], LDS, wmma::mem_row_major);
    __syncthreads();

    const int er = tid >> 1;
    const int ec = (tid & 1) * 64;
    __half* dst = C + (long)(tm + er) * N + tn + ec;
#pragma unroll
    for (int c = 0; c < 64; c += 8) {
        __half2 h2[4];
#pragma unroll
        for (int u = 0; u < 4; u++)
            h2[u] = __floats2half2_rn(st[er * LDS + ec + c + u * 2],
                                      st[er * LDS + ec + c + u * 2 + 1]);
        *(uint4*)&dst[c] = *(uint4*)h2;
    }
}

// ===========================================================================
// Scores + exp:  E = exp(A B^T / 32), fp16 in, fp16 E out + partial row sums.
// 256 threads, 8 warps (4x2), warp 32x64, BK=64, 3-stage one-sync pipeline.
// ===========================================================================
__global__ void __launch_bounds__(256, 2) gemm_scores_exp(
    const __half* __restrict__ Ab, const __half* __restrict__ Bb,
    __half* __restrict__ Pb, float* __restrict__ partial,
    int N, int K, long sA, long sB, long sP, float alpha)
{
    constexpr int BM = 128, BN = 128, BK = 64, LD = BK + 8;
    constexpr int LDS = 132;
    extern __shared__ __align__(16) char smraw[];
    __half* As = (__half*)smraw;       // [3][BM][LD]
    __half* Bs = As + 3 * BM * LD;

    const __half* A = Ab + (long)blockIdx.z * sA;
    const __half* B = Bb + (long)blockIdx.z * sB;
    __half*       P = Pb + (long)blockIdx.z * sP;

    const int tm   = blockIdx.y * BM;
    const int tn   = blockIdx.x * BN;
    const int tid  = threadIdx.x;
    const int warp = tid >> 5;
    const int wm   = (warp >> 1) * 32;
    const int wn   = (warp & 1) * 64;

    wmma::fragment<wmma::accumulator, 16, 16, 16, float> acc[2][4];
#pragma unroll
    for (int i = 0; i < 2; i++)
#pragma unroll
        for (int j = 0; j < 4; j++) wmma::fill_fragment(acc[i][j], 0.0f);

    const int lr = tid >> 1;
    const int lc = (tid & 1) * 32;

    auto load_tile = [&](int buf, int kk) {
        long ga = (long)(tm + lr) * K + kk + lc;
        long gb = (long)(tn + lr) * K + kk + lc;
        int  sa = (buf * BM + lr) * LD + lc;
        int  sb = (buf * BN + lr) * LD + lc;
#pragma unroll
        for (int j = 0; j < 4; j++) {
            cp_async16(&As[sa + j * 8], &A[ga + j * 8]);
            cp_async16(&Bs[sb + j * 8], &B[gb + j * 8]);
        }
        cp_commit();
    };

    const int NCH = K / BK;
    load_tile(0, 0);
    load_tile(1, BK);

    int buf = 0;
    for (int c = 0; c < NCH; c++) {
        if (c + 1 < NCH) cp_wait1(); else cp_wait0();
        __syncthreads();

#pragma unroll
        for (int ks = 0; ks < BK; ks += 16) {
            wmma::fragment<wmma::matrix_a, 16, 16, 16, __half, wmma::row_major> af[2];
            wmma::fragment<wmma::matrix_b, 16, 16, 16, __half, wmma::col_major> bf[4];
#pragma unroll
            for (int i = 0; i < 2; i++)
                wmma::load_matrix_sync(af[i], &As[(buf * BM + wm + i * 16) * LD + ks], LD);
#pragma unroll
            for (int j = 0; j < 4; j++)
                wmma::load_matrix_sync(bf[j], &Bs[(buf * BN + wn + j * 16) * LD + ks], LD);
#pragma unroll
            for (int i = 0; i < 2; i++)
#pragma unroll
                for (int j = 0; j < 4; j++)
                    wmma::mma_sync(acc[i][j], af[i], bf[j], acc[i][j]);
        }

        if (c + 2 < NCH) {
            int nb = buf + 2; if (nb >= 3) nb -= 3;
            load_tile(nb, (c + 2) * BK);
        }
        buf = (buf + 1 == 3) ? 0 : buf + 1;
    }

    // Epilogue: stage, exp (f16x2), write fp16 E, emit partial row sums.
    float* st = (float*)smraw;      // [128][LDS]
    __syncthreads();
#pragma unroll
    for (int i = 0; i < 2; i++)
#pragma unroll
        for (int j = 0; j < 4; j++)
            wmma::store_matrix_sync(&st[(wm + i * 16) * LDS + wn + j * 16],
                                    acc[i][j], LDS, wmma::mem_row_major);
    __syncthreads();

    const int er = tid >> 1;
    const int ec = (tid & 1) * 64;
    __half* dst = P + (long)(tm + er) * N + tn + ec;
    float sum = 0.0f;
#pragma unroll
    for (int c = 0; c < 64; c += 8) {
        __half2 e2[4];
#pragma unroll
        for (int u = 0; u < 4; u++) {
            float x0 = st[er * LDS + ec + c + u * 2]     * alpha;
            float x1 = st[er * LDS + ec + c + u * 2 + 1] * alpha;
            e2[u] = h2exp(__floats2half2_rn(x0, x1));
            float2 ef = __half22float2(e2[u]);
            sum += ef.x + ef.y;
        }
        *(uint4*)&dst[c] = *(uint4*)e2;
    }
    partial[((long)blockIdx.z * SQ + tm + er) * 64 + blockIdx.x * 2 + (tid & 1)] = sum;
}

// ===========================================================================
// Deterministic row-sum reduction: rowsum[r] = sum of 64 partials.
// ===========================================================================
__global__ void __launch_bounds__(256) reduce_rowsum(
    const float* __restrict__ partial, float* __restrict__ rowsum)
{
    int row  = blockIdx.x * 8 + (threadIdx.x >> 5);
    int lane = threadIdx.x & 31;
    const float* pr = partial + (long)row * 64;
    float s = pr[lane] + pr[lane + 32];
#pragma unroll
    for (int o = 16; o; o >>= 1) s += __shfl_xor_sync(0xffffffffu, s, o);
    if (lane == 0) rowsum[row] = s;
}

// ===========================================================================
// PV + normalize:  out = (E V) / rowsum, fp16 in, fp32 out.
// ===========================================================================
__global__ void __launch_bounds__(256, 2) gemm_pv_div(
    const __half* __restrict__ Ab, const __half* __restrict__ Bb,
    float* __restrict__ Cb, const float* __restrict__ rowsum,
    int N, int K, long sA, long sB, long sC)
{
    constexpr int BM = 128, BN = 128, BK = 64, LDA = BK + 8, LDB = BN + 8;
    constexpr int LDS = 132;
    extern __shared__ __align__(16) char smraw[];
    __half* As = (__half*)smraw;        // [3][BM][LDA]
    __half* Bs = As + 3 * BM * LDA;     // [3][BK][LDB]

    const __half* A = Ab + (long)blockIdx.z * sA;
    const __half* B = Bb + (long)blockIdx.z * sB;
    float*        C = Cb + (long)blockIdx.z * sC;

    const int tm   = blockIdx.y * BM;
    const int tn   = blockIdx.x * BN;
    const int tid  = threadIdx.x;
    const int warp = tid >> 5;
    const int wm   = (warp >> 1) * 32;
    const int wn   = (warp & 1) * 64;

    wmma::fragment<wmma::accumulator, 16, 16, 16, float> acc[2][4];
#pragma unroll
    for (int i = 0; i < 2; i++)
#pragma unroll
        for (int j = 0; j < 4; j++) wmma::fill_fragment(acc[i][j], 0.0f);

    const int ar = tid >> 1;
    const int ac = (tid & 1) * 32;
    const int br = tid >> 2;
    const int bc = tid & 3;

    auto load_tile = [&](int buf, int kk) {
        long ga = (long)(tm + ar) * K + kk + ac;
        int  sa = (buf * BM + ar) * LDA + ac;
#pragma unroll
        for (int j = 0; j < 4; j++)
            cp_async16(&As[sa + j * 8], &A[ga + j * 8]);
        long gb = (long)(kk + br) * N + tn;
        int  sb = (buf * BK + br) * LDB;
#pragma unroll
        for (int j = 0; j < 4; j++) {
            int ch = bc + j * 4;
            cp_async16(&Bs[sb + ch * 8], &B[gb + ch * 8]);
        }
        cp_commit();
    };

    const int NCH = K / BK;
    load_tile(0, 0);
    load_tile(1, BK);

    int buf = 0;
    for (int c = 0; c < NCH; c++) {
        if (c + 1 < NCH) cp_wait1(); else cp_wait0();
        __syncthreads();

#pragma unroll
        for (int ks = 0; ks < BK; ks += 16) {
            wmma::fragment<wmma::matrix_a, 16, 16, 16, __half, wmma::row_major> af[2];
            wmma::fragment<wmma::matrix_b, 16, 16, 16, __half, wmma::row_major> bf[4];
#pragma unroll
            for (int i = 0; i < 2; i++)
                wmma::load_matrix_sync(af[i], &As[(buf * BM + wm + i * 16) * LDA + ks], LDA);
#pragma unroll
            for (int j = 0; j < 4; j++)
                wmma::load_matrix_sync(bf[j], &Bs[(buf * BK + ks) * LDB + wn + j * 16], LDB);
#pragma unroll
            for (int i = 0; i < 2; i++)
#pragma unroll
                for (int j = 0; j < 4; j++)
                    wmma::mma_sync(acc[i][j], af[i], bf[j], acc[i][j]);
        }

        if (c + 2 < NCH) {
            int nb = buf + 2; if (nb >= 3) nb -= 3;
            load_tile(nb, (c + 2) * BK);
        }
        buf = (buf + 1 == 3) ? 0 : buf + 1;
    }

    // Epilogue: stage, divide by row sum, write fp32.
    float* st = (float*)smraw;      // [128][LDS]
    __syncthreads();
#pragma unroll
    for (int i = 0; i < 2; i++)
#pragma unroll
        for (int j = 0; j < 4; j++)
            wmma::store_matrix_sync(&st[(wm + i * 16) * LDS + wn + j * 16],
                                    acc[i][j], LDS, wmma::mem_row_major);
    __syncthreads();

    const int er = tid >> 1;
    const int ec = (tid & 1) * 64;
    const float inv = 1.0f / rowsum[(long)blockIdx.z * SQ + tm + er];
    float* dst = C + (long)(tm + er) * N + tn + ec;
#pragma unroll
    for (int c = 0; c < 64; c += 4) {
        float4 v;
        v.x = st[er * LDS + ec + c + 0] * inv;
        v.y = st[er * LDS + ec + c + 1] * inv;
        v.z = st[er * LDS + ec + c + 2] * inv;
        v.w = st[er * LDS + ec + c + 3] * inv;
        *(float4*)&dst[c] = v;
    }
}

// ---------------------------------------------------------------------------
extern "C" void kernel_launch(void* const* d_in, const int* in_sizes, int n_in,
                              void* d_out, int out_size)
{
    const float* x  = (const float*)d_in[0];
    const float* Wq = (const float*)d_in[1];
    const float* Wk = (const float*)d_in[2];
    const float* Wv = (const float*)d_in[3];
    float* out = (float*)d_out;

    __half *qh, *kh, *vh, *p;
    __nv_bfloat16 *xh, *xl, *wh, *wl;
    float *partial, *rowsum;
    cudaGetSymbolAddress((void**)&qh, g_qh);
    cudaGetSymbolAddress((void**)&kh, g_kh);
    cudaGetSymbolAddress((void**)&vh, g_vh);
    cudaGetSymbolAddress((void**)&p,  g_p);
    cudaGetSymbolAddress((void**)&xh, g_xh);
    cudaGetSymbolAddress((void**)&xl, g_xl);
    cudaGetSymbolAddress((void**)&wh, g_wh);
    cudaGetSymbolAddress((void**)&wl, g_wl);
    cudaGetSymbolAddress((void**)&partial, g_partial);
    cudaGetSymbolAddress((void**)&rowsum,  g_rowsum);

    const int smem_qkv = 2 * 4 * 128 * 48 * 2;            // 98304
    const int smem_sc  = 3 * 2 * 128 * 72 * 2;            // 110592
    const int smem_pv  = 3 * (128 * 72 + 64 * 136) * 2;   // 107520

    cudaFuncSetAttribute(gemm_qkv_bf16,   cudaFuncAttributeMaxDynamicSharedMemorySize, smem_qkv);
    cudaFuncSetAttribute(gemm_scores_exp, cudaFuncAttributeMaxDynamicSharedMemorySize, smem_sc);
    cudaFuncSetAttribute(gemm_pv_div,     cudaFuncAttributeMaxDynamicSharedMemorySize, smem_pv);

    const int nx = NB * SQ * DM;
    const int nw = DM * DM;

    // Phase 0: hi/lo bf16 splits of inputs.
    split_bf16<<<nx / 4 / 256, 256>>>(x,  xh, xl, nx);
    split_bf16<<<nw / 4 / 256, 256>>>(Wq, wh + 0L * nw, wl + 0L * nw, nw);
    split_bf16<<<nw / 4 / 256, 256>>>(Wk, wh + 1L * nw, wl + 1L * nw, nw);
    split_bf16<<<nw / 4 / 256, 256>>>(Wv, wh + 2L * nw, wl + 2L * nw, nw);

    // Phase 1: QKV projections (3-term bf16), fp16 out directly.
    {
        dim3 grid(DM / 128, (NB * SQ) / 128, 1);
        gemm_qkv_bf16<<<grid, 256, smem_qkv>>>(xh, xl, wh + 0L * nw, wl + 0L * nw, qh, DM, DM);
        gemm_qkv_bf16<<<grid, 256, smem_qkv>>>(xh, xl, wh + 1L * nw, wl + 1L * nw, kh, DM, DM);
        gemm_qkv_bf16<<<grid, 256, smem_qkv>>>(xh, xl, wh + 2L * nw, wl + 2L * nw, vh, DM, DM);
    }

    // Phase 2: E = exp(Q K^T / 32) (fp16), plus partial row sums.
    {
        dim3 grid(SQ / 128, SQ / 128, NB);
        gemm_scores_exp<<<grid, 256, smem_sc>>>(qh, kh, p, partial, SQ, DM,
                                                (long)SQ * DM, (long)SQ * DM,
                                                (long)SQ * SQ, 1.0f / 32.0f);
    }

    // Phase 3: deterministic row-sum reduction.
    reduce_rowsum<<<NB * SQ / 8, 256>>>(partial, rowsum);

    // Phase 4: out = (E V) / rowsum.
    {
        dim3 grid(DM / 128, SQ / 128, NB);
        gemm_pv_div<<<grid, 256, smem_pv>>>(p, vh, out, rowsum, DM, SQ,
                                            (long)SQ * SQ, (long)SQ * DM,
                                            (long)SQ * DM);
    }
}

// round 17
// speedup vs baseline: 2.0825x; 2.0825x over previous
#include <cuda_runtime.h>
#include <cstdint>
#include <mma.h>
#include <math.h>
#include <cuda_bf16.h>
#include <cuda_fp16.h>

using namespace nvcuda;

#define DM   1024
#define NB   4
#define SQ   4096

// Scratch (device globals: the sanctioned alloc-free workaround)
__device__ float g_q[(size_t)NB * SQ * DM];   // T (1024x1024) lives here
__device__ float g_k[(size_t)NB * SQ * DM];   // WkT early; A_scores fp32 later
__device__ float g_v[(size_t)NB * SQ * DM];   // WqT early; V fp32 later
__device__ float g_s[(size_t)NB * SQ * SQ];
__device__ __half g_qh[(size_t)NB * SQ * DM];
__device__ __half g_kh[(size_t)NB * SQ * DM];
__device__ __half g_vh[(size_t)NB * SQ * DM];
__device__ __half g_p [(size_t)NB * SQ * SQ];
__device__ __nv_bfloat16 g_xh[(size_t)NB * SQ * DM];
__device__ __nv_bfloat16 g_xl[(size_t)NB * SQ * DM];
__device__ __nv_bfloat16 g_wh[4][(size_t)DM * DM];  // 0:T 1:Wv 2:WqT 3:WkT
__device__ __nv_bfloat16 g_wl[4][(size_t)DM * DM];

__device__ __forceinline__ void cp_async16(void* dst_smem, const void* src_gmem)
{
    uint32_t d = (uint32_t)__cvta_generic_to_shared(dst_smem);
    asm volatile("cp.async.cg.shared.global [%0], [%1], 16;\n" :: "r"(d), "l"(src_gmem));
}
__device__ __forceinline__ void cp_commit() { asm volatile("cp.async.commit_group;\n" ::); }
__device__ __forceinline__ void cp_wait0()  { asm volatile("cp.async.wait_group 0;\n" ::); }
__device__ __forceinline__ void cp_wait1()  { asm volatile("cp.async.wait_group 1;\n" ::); }

// ===========================================================================
// Elementwise split: fp32 -> bf16 hi + bf16 lo.
// ===========================================================================
__global__ void __launch_bounds__(256) split_bf16(
    const float* __restrict__ in, __nv_bfloat16* __restrict__ h,
    __nv_bfloat16* __restrict__ l, int n)
{
    int idx = (blockIdx.x * 256 + threadIdx.x) * 4;
    if (idx >= n) return;
    float4 v = *(const float4*)&in[idx];
    __nv_bfloat16 h0 = __float2bfloat16_rn(v.x);
    __nv_bfloat16 h1 = __float2bfloat16_rn(v.y);
    __nv_bfloat16 h2 = __float2bfloat16_rn(v.z);
    __nv_bfloat16 h3 = __float2bfloat16_rn(v.w);
    __nv_bfloat16 l0 = __float2bfloat16_rn(v.x - __bfloat162float(h0));
    __nv_bfloat16 l1 = __float2bfloat16_rn(v.y - __bfloat162float(h1));
    __nv_bfloat16 l2 = __float2bfloat16_rn(v.z - __bfloat162float(h2));
    __nv_bfloat16 l3 = __float2bfloat16_rn(v.w - __bfloat162float(h3));
    ushort4 hv = { __bfloat16_as_ushort(h0), __bfloat16_as_ushort(h1),
                   __bfloat16_as_ushort(h2), __bfloat16_as_ushort(h3) };
    ushort4 lv = { __bfloat16_as_ushort(l0), __bfloat16_as_ushort(l1),
                   __bfloat16_as_ushort(l2), __bfloat16_as_ushort(l3) };
    *(ushort4*)&h[idx] = hv;
    *(ushort4*)&l[idx] = lv;
}

// ===========================================================================
// Elementwise convert fp32 -> fp16 (RN).
// ===========================================================================
__global__ void __launch_bounds__(256) cvt_f16(
    const float* __restrict__ in, __half* __restrict__ out, int n)
{
    int idx = (blockIdx.x * 256 + threadIdx.x) * 4;
    if (idx >= n) return;
    float4 v = *(const float4*)&in[idx];
    ushort4 o = { __half_as_ushort(__float2half_rn(v.x)),
                  __half_as_ushort(__float2half_rn(v.y)),
                  __half_as_ushort(__float2half_rn(v.z)),
                  __half_as_ushort(__float2half_rn(v.w)) };
    *(ushort4*)&out[idx] = o;
}

// ===========================================================================
// 32x32-tiled fp32 transpose: out[i][j] = in[j][i], n x n.
// ===========================================================================
__global__ void __launch_bounds__(256) transpose_f32(
    const float* __restrict__ in, float* __restrict__ out, int n)
{
    __shared__ float t[32][33];
    int x = blockIdx.x * 32 + threadIdx.x;
    int y = blockIdx.y * 32 + threadIdx.y;
#pragma unroll
    for (int i = 0; i < 32; i += 8)
        t[threadIdx.y + i][threadIdx.x] = in[(long)(y + i) * n + x];
    __syncthreads();
    x = blockIdx.y * 32 + threadIdx.x;
    y = blockIdx.x * 32 + threadIdx.y;
#pragma unroll
    for (int i = 0; i < 32; i += 8)
        out[(long)(y + i) * n + x] = t[threadIdx.x][threadIdx.y + i];
}

// ===========================================================================
// 3-term bf16 GEMM: C(M,N) = (Ah+Al)(M,K) x (Bh+Bl)(N,K)^T, fp32 out.
// grid.z selects weight slice (Wh/Wl + z*N*K) and output (z ? C1 : C0).
// Direct wmma stores; 2-stage cp.async. (round-13-proven mainloop)
// ===========================================================================
__global__ void __launch_bounds__(256, 2) gemm_abT_bf3(
    const __nv_bfloat16* __restrict__ Ah, const __nv_bfloat16* __restrict__ Al,
    const __nv_bfloat16* __restrict__ Wh, const __nv_bfloat16* __restrict__ Wl,
    float* __restrict__ C0, float* __restrict__ C1, int N, int K)
{
    constexpr int BM = 128, BN = 128, BK = 32, LD = BK + 16;
    extern __shared__ __align__(16) char smraw[];
    __nv_bfloat16* sAh = (__nv_bfloat16*)smraw;
    __nv_bfloat16* sAl = sAh + 2 * BM * LD;
    __nv_bfloat16* sBh = sAh + 4 * BM * LD;
    __nv_bfloat16* sBl = sAh + 6 * BM * LD;

    const __nv_bfloat16* Bh = Wh + (long)blockIdx.z * N * K;
    const __nv_bfloat16* Bl = Wl + (long)blockIdx.z * N * K;
    float* C = blockIdx.z ? C1 : C0;

    const int tm   = blockIdx.y * BM;
    const int tn   = blockIdx.x * BN;
    const int tid  = threadIdx.x;
    const int warp = tid >> 5;
    const int wm   = (warp >> 1) * 32;
    const int wn   = (warp & 1) * 64;

    wmma::fragment<wmma::accumulator, 16, 16, 16, float> acc[2][4];
#pragma unroll
    for (int i = 0; i < 2; i++)
#pragma unroll
        for (int j = 0; j < 4; j++) wmma::fill_fragment(acc[i][j], 0.0f);

    const int lr = tid >> 1;
    const int lc = (tid & 1) * 16;

    auto load_tile = [&](int buf, int kk) {
        long ga = (long)(tm + lr) * K + kk + lc;
        long gb = (long)(tn + lr) * K + kk + lc;
        int  sa = (buf * BM + lr) * LD + lc;
        int  sb = (buf * BN + lr) * LD + lc;
        cp_async16(&sAh[sa],     &Ah[ga]);
        cp_async16(&sAh[sa + 8], &Ah[ga + 8]);
        cp_async16(&sAl[sa],     &Al[ga]);
        cp_async16(&sAl[sa + 8], &Al[ga + 8]);
        cp_async16(&sBh[sb],     &Bh[gb]);
        cp_async16(&sBh[sb + 8], &Bh[gb + 8]);
        cp_async16(&sBl[sb],     &Bl[gb]);
        cp_async16(&sBl[sb + 8], &Bl[gb + 8]);
        cp_commit();
    };

    load_tile(0, 0);
    int buf = 0;
    for (int kk = 0; kk < K; kk += BK) {
        const bool has_next = (kk + BK) < K;
        if (has_next) {
            load_tile(buf ^ 1, kk + BK);
            cp_wait1();
        } else {
            cp_wait0();
        }
        __syncthreads();

#pragma unroll
        for (int ks = 0; ks < BK; ks += 16) {
            wmma::fragment<wmma::matrix_a, 16, 16, 16, __nv_bfloat16, wmma::row_major> ah[2], al[2];
            wmma::fragment<wmma::matrix_b, 16, 16, 16, __nv_bfloat16, wmma::col_major> bh[4], bl[4];
#pragma unroll
            for (int i = 0; i < 2; i++) {
                wmma::load_matrix_sync(ah[i], &sAh[(buf * BM + wm + i * 16) * LD + ks], LD);
                wmma::load_matrix_sync(al[i], &sAl[(buf * BM + wm + i * 16) * LD + ks], LD);
            }
#pragma unroll
            for (int j = 0; j < 4; j++) {
                wmma::load_matrix_sync(bh[j], &sBh[(buf * BN + wn + j * 16) * LD + ks], LD);
                wmma::load_matrix_sync(bl[j], &sBl[(buf * BN + wn + j * 16) * LD + ks], LD);
            }
#pragma unroll
            for (int i = 0; i < 2; i++)
#pragma unroll
                for (int j = 0; j < 4; j++) {
                    wmma::mma_sync(acc[i][j], ah[i], bl[j], acc[i][j]);
                    wmma::mma_sync(acc[i][j], al[i], bh[j], acc[i][j]);
                    wmma::mma_sync(acc[i][j], ah[i], bh[j], acc[i][j]);
                }
        }
        __syncthreads();
        buf ^= 1;
    }

#pragma unroll
    for (int i = 0; i < 2; i++)
#pragma unroll
        for (int j = 0; j < 4; j++)
            wmma::store_matrix_sync(&C[(long)(tm + wm + i * 16) * N + tn + wn + j * 16],
                                    acc[i][j], N, wmma::mem_row_major);
}

// ===========================================================================
// FP16:  C = alpha * A(M,K) * B(N,K)^T, fp32 accum/out. (round-13 exact)
// ===========================================================================
__global__ void __launch_bounds__(256, 2) gemm_abT_f16(
    const __half* __restrict__ Ab, const __half* __restrict__ Bb,
    float* __restrict__ Cb, int N, int K,
    long sA, long sB, long sC, float alpha)
{
    constexpr int BM = 128, BN = 128, BK = 64, LD = BK + 8;
    extern __shared__ __align__(16) char smraw[];
    __half* As = (__half*)smraw;       // [3][BM][LD]
    __half* Bs = As + 3 * BM * LD;     // [3][BN][LD]

    const __half* A = Ab + (long)blockIdx.z * sA;
    const __half* B = Bb + (long)blockIdx.z * sB;
    float*        C = Cb + (long)blockIdx.z * sC;

    const int tm   = blockIdx.y * BM;
    const int tn   = blockIdx.x * BN;
    const int tid  = threadIdx.x;
    const int warp = tid >> 5;
    const int wm   = (warp >> 1) * 32;
    const int wn   = (warp & 1) * 64;

    wmma::fragment<wmma::accumulator, 16, 16, 16, float> acc[2][4];
#pragma unroll
    for (int i = 0; i < 2; i++)
#pragma unroll
        for (int j = 0; j < 4; j++) wmma::fill_fragment(acc[i][j], 0.0f);

    const int lr = tid >> 1;
    const int lc = (tid & 1) * 32;

    auto load_tile = [&](int buf, int kk) {
        long ga = (long)(tm + lr) * K + kk + lc;
        long gb = (long)(tn + lr) * K + kk + lc;
        int  sa = (buf * BM + lr) * LD + lc;
        int  sb = (buf * BN + lr) * LD + lc;
#pragma unroll
        for (int j = 0; j < 4; j++) {
            cp_async16(&As[sa + j * 8], &A[ga + j * 8]);
            cp_async16(&Bs[sb + j * 8], &B[gb + j * 8]);
        }
        cp_commit();
    };

    const int NCH = K / BK;
    load_tile(0, 0);
    load_tile(1, BK);

    int buf = 0;
    for (int c = 0; c < NCH; c++) {
        if (c + 1 < NCH) cp_wait1(); else cp_wait0();
        __syncthreads();

#pragma unroll
        for (int ks = 0; ks < BK; ks += 16) {
            wmma::fragment<wmma::matrix_a, 16, 16, 16, __half, wmma::row_major> af[2];
            wmma::fragment<wmma::matrix_b, 16, 16, 16, __half, wmma::col_major> bf[4];
#pragma unroll
            for (int i = 0; i < 2; i++)
                wmma::load_matrix_sync(af[i], &As[(buf * BM + wm + i * 16) * LD + ks], LD);
#pragma unroll
            for (int j = 0; j < 4; j++)
                wmma::load_matrix_sync(bf[j], &Bs[(buf * BN + wn + j * 16) * LD + ks], LD);
#pragma unroll
            for (int i = 0; i < 2; i++)
#pragma unroll
                for (int j = 0; j < 4; j++)
                    wmma::mma_sync(acc[i][j], af[i], bf[j], acc[i][j]);
        }

        if (c + 2 < NCH) {
            int nb = buf + 2; if (nb >= 3) nb -= 3;
            load_tile(nb, (c + 2) * BK);
        }
        buf = (buf + 1 == 3) ? 0 : buf + 1;
    }

#pragma unroll
    for (int i = 0; i < 2; i++)
#pragma unroll
        for (int j = 0; j < 4; j++) {
#pragma unroll
            for (int e = 0; e < acc[i][j].num_elements; e++) acc[i][j].x[e] *= alpha;
            wmma::store_matrix_sync(&C[(long)(tm + wm + i * 16) * N + tn + wn + j * 16],
                                    acc[i][j], N, wmma::mem_row_major);
        }
}

// ===========================================================================
// FP16:  C = A(M,K) * B(K,N), fp32 accum/out. (round-13 exact)
// ===========================================================================
__global__ void __launch_bounds__(256, 2) gemm_ab_f16(
    const __half* __restrict__ Ab, const __half* __restrict__ Bb,
    float* __restrict__ Cb, int N, int K,
    long sA, long sB, long sC)
{
    constexpr int BM = 128, BN = 128, BK = 64, LDA = BK + 8, LDB = BN + 8;
    extern __shared__ __align__(16) char smraw[];
    __half* As = (__half*)smraw;        // [3][BM][LDA]
    __half* Bs = As + 3 * BM * LDA;     // [3][BK][LDB]

    const __half* A = Ab + (long)blockIdx.z * sA;
    const __half* B = Bb + (long)blockIdx.z * sB;
    float*        C = Cb + (long)blockIdx.z * sC;

    const int tm   = blockIdx.y * BM;
    const int tn   = blockIdx.x * BN;
    const int tid  = threadIdx.x;
    const int warp = tid >> 5;
    const int wm   = (warp >> 1) * 32;
    const int wn   = (warp & 1) * 64;

    wmma::fragment<wmma::accumulator, 16, 16, 16, float> acc[2][4];
#pragma unroll
    for (int i = 0; i < 2; i++)
#pragma unroll
        for (int j = 0; j < 4; j++) wmma::fill_fragment(acc[i][j], 0.0f);

    const int ar = tid >> 1;
    const int ac = (tid & 1) * 32;
    const int br = tid >> 2;
    const int bc = tid & 3;

    auto load_tile = [&](int buf, int kk) {
        long ga = (long)(tm + ar) * K + kk + ac;
        int  sa = (buf * BM + ar) * LDA + ac;
#pragma unroll
        for (int j = 0; j < 4; j++)
            cp_async16(&As[sa + j * 8], &A[ga + j * 8]);
        long gb = (long)(kk + br) * N + tn;
        int  sb = (buf * BK + br) * LDB;
#pragma unroll
        for (int j = 0; j < 4; j++) {
            int ch = bc + j * 4;
            cp_async16(&Bs[sb + ch * 8], &B[gb + ch * 8]);
        }
        cp_commit();
    };

    const int NCH = K / BK;
    load_tile(0, 0);
    load_tile(1, BK);

    int buf = 0;
    for (int c = 0; c < NCH; c++) {
        if (c + 1 < NCH) cp_wait1(); else cp_wait0();
        __syncthreads();

#pragma unroll
        for (int ks = 0; ks < BK; ks += 16) {
            wmma::fragment<wmma::matrix_a, 16, 16, 16, __half, wmma::row_major> af[2];
            wmma::fragment<wmma::matrix_b, 16, 16, 16, __half, wmma::row_major> bf[4];
#pragma unroll
            for (int i = 0; i < 2; i++)
                wmma::load_matrix_sync(af[i], &As[(buf * BM + wm + i * 16) * LDA + ks], LDA);
#pragma unroll
            for (int j = 0; j < 4; j++)
                wmma::load_matrix_sync(bf[j], &Bs[(buf * BK + ks) * LDB + wn + j * 16], LDB);
#pragma unroll
            for (int i = 0; i < 2; i++)
#pragma unroll
                for (int j = 0; j < 4; j++)
                    wmma::mma_sync(acc[i][j], af[i], bf[j], acc[i][j]);
        }

        if (c + 2 < NCH) {
            int nb = buf + 2; if (nb >= 3) nb -= 3;
            load_tile(nb, (c + 2) * BK);
        }
        buf = (buf + 1 == 3) ? 0 : buf + 1;
    }

#pragma unroll
    for (int i = 0; i < 2; i++)
#pragma unroll
        for (int j = 0; j < 4; j++)
            wmma::store_matrix_sync(&C[(long)(tm + wm + i * 16) * N + tn + wn + j * 16],
                                    acc[i][j], N, wmma::mem_row_major);
}

// ---------------------------------------------------------------------------
// Row softmax over 4096-wide rows; f16x2 exp; writes fp16 probabilities.
// (round-13 exact)
// ---------------------------------------------------------------------------
__global__ void __launch_bounds__(256) softmax_f16_safe(
    const float* __restrict__ Sg, __half* __restrict__ P)
{
    const float* row = Sg + (size_t)blockIdx.x * SQ;
    __half* prow = P + (size_t)blockIdx.x * SQ;
    const int tid = threadIdx.x;
    __shared__ float red[8];

    float vals[16];
    float m = -3.4e38f;
#pragma unroll
    for (int i = 0; i < 16; i++) {
        vals[i] = row[tid + i * 256];
        m = fmaxf(m, vals[i]);
    }
#pragma unroll
    for (int o = 16; o; o >>= 1) m = fmaxf(m, __shfl_xor_sync(0xffffffffu, m, o));
    if ((tid & 31) == 0) red[tid >> 5] = m;
    __syncthreads();
    {
        float t = red[tid & 7];
#pragma unroll
        for (int o = 4; o; o >>= 1) t = fmaxf(t, __shfl_xor_sync(0xffffffffu, t, o));
        m = t;
    }

    float sum = 0.0f;
#pragma unroll
    for (int i = 0; i < 8; i++) {
        __half2 x = __floats2half2_rn(vals[2 * i] - m, vals[2 * i + 1] - m);
        float2 e = __half22float2(h2exp(x));
        vals[2 * i]     = e.x;
        vals[2 * i + 1] = e.y;
        sum += e.x + e.y;
    }
#pragma unroll
    for (int o = 16; o; o >>= 1) sum += __shfl_xor_sync(0xffffffffu, sum, o);
    __syncthreads();
    if ((tid & 31) == 0) red[tid >> 5] = sum;
    __syncthreads();
    {
        float t = red[tid & 7];
#pragma unroll
        for (int o = 4; o; o >>= 1) t += __shfl_xor_sync(0xffffffffu, t, o);
        sum = t;
    }

    float inv = 1.0f / sum;
#pragma unroll
    for (int i = 0; i < 16; i++)
        prow[tid + i * 256] = __float2half_rn(vals[i] * inv);
}

// ---------------------------------------------------------------------------
extern "C" void kernel_launch(void* const* d_in, const int* in_sizes, int n_in,
                              void* d_out, int out_size)
{
    const float* x  = (const float*)d_in[0];
    const float* Wq = (const float*)d_in[1];
    const float* Wk = (const float*)d_in[2];
    const float* Wv = (const float*)d_in[3];
    float* out = (float*)d_out;

    float *q, *k, *v, *s;
    __half *qh, *kh, *vh, *p;
    __nv_bfloat16 *xh, *xl, *wh, *wl;
    cudaGetSymbolAddress((void**)&q,  g_q);
    cudaGetSymbolAddress((void**)&k,  g_k);
    cudaGetSymbolAddress((void**)&v,  g_v);
    cudaGetSymbolAddress((void**)&s,  g_s);
    cudaGetSymbolAddress((void**)&qh, g_qh);
    cudaGetSymbolAddress((void**)&kh, g_kh);
    cudaGetSymbolAddress((void**)&vh, g_vh);
    cudaGetSymbolAddress((void**)&p,  g_p);
    cudaGetSymbolAddress((void**)&xh, g_xh);
    cudaGetSymbolAddress((void**)&xl, g_xl);
    cudaGetSymbolAddress((void**)&wh, g_wh);
    cudaGetSymbolAddress((void**)&wl, g_wl);

    const int smem_bf3 = 2 * 4 * 128 * 48 * 2;             // 98304
    const int smem_abT = 3 * 2 * 128 * 72 * 2;             // 110592
    const int smem_ab  = 3 * (128 * 72 + 64 * 136) * 2;    // 107520

    cudaFuncSetAttribute(gemm_abT_bf3, cudaFuncAttributeMaxDynamicSharedMemorySize, smem_bf3);
    cudaFuncSetAttribute(gemm_abT_f16, cudaFuncAttributeMaxDynamicSharedMemorySize, smem_abT);
    cudaFuncSetAttribute(gemm_ab_f16,  cudaFuncAttributeMaxDynamicSharedMemorySize, smem_ab);

    const int nx = NB * SQ * DM;       // 16,777,216
    const int nw = DM * DM;            // 1,048,576

    // Phase 0a: split x; transpose Wq, Wk (into g_v / g_k scratch).
    split_bf16<<<nx / 4 / 256, 256>>>(x, xh, xl, nx);
    {
        dim3 tg(DM / 32, DM / 32);
        transpose_f32<<<tg, dim3(32, 8)>>>(Wq, v, DM);   // WqT -> g_v
        transpose_f32<<<tg, dim3(32, 8)>>>(Wk, k, DM);   // WkT -> g_k
    }
    // Phase 0b: split WqT -> slot2, WkT -> slot3, Wv -> slot1.
    split_bf16<<<nw / 4 / 256, 256>>>(v,  wh + 2L * nw, wl + 2L * nw, nw);
    split_bf16<<<nw / 4 / 256, 256>>>(k,  wh + 3L * nw, wl + 3L * nw, nw);
    split_bf16<<<nw / 4 / 256, 256>>>(Wv, wh + 1L * nw, wl + 1L * nw, nw);

    // Phase 0c: T = M2^T = abT(WkT, WqT) -> g_q (fp32), then split -> slot0.
    {
        dim3 grid(DM / 128, DM / 128, 1);
        gemm_abT_bf3<<<grid, 256, smem_bf3>>>(wh + 3L * nw, wl + 3L * nw,
                                              wh + 2L * nw, wl + 2L * nw,
                                              q, q, DM, DM);
    }
    split_bf16<<<nw / 4 / 256, 256>>>(q, wh + 0L * nw, wl + 0L * nw, nw);

    // Phase 1: merged projections. z=0: A_scores = x*M2 (B = T, slot0) -> g_k.
    //          z=1: V = x*Wv^T (B = Wv, slot1) -> g_v.
    {
        dim3 grid(DM / 128, (NB * SQ) / 128, 2);
        gemm_abT_bf3<<<grid, 256, smem_bf3>>>(xh, xl, wh, wl, k, v, DM, DM);
    }

    // Phase 1b: fp16 conversions: A_scores -> qh, x -> kh, V -> vh.
    cvt_f16<<<nx / 4 / 256, 256>>>(k, qh, nx);
    cvt_f16<<<nx / 4 / 256, 256>>>(x, kh, nx);
    cvt_f16<<<nx / 4 / 256, 256>>>(v, vh, nx);

    // Phase 2: scores = (A_scores x^T) / 32, fp16 inputs, fp32 out.
    {
        dim3 grid(SQ / 128, SQ / 128, NB);
        gemm_abT_f16<<<grid, 256, smem_abT>>>(qh, kh, s, SQ, DM,
                                              (long)SQ * DM, (long)SQ * DM,
                                              (long)SQ * SQ, 1.0f / 32.0f);
    }

    // Phase 3: softmax -> fp16 P.
    softmax_f16_safe<<<NB * SQ, 256>>>(s, p);

    // Phase 4: out = P V, fp16 inputs, fp32 out.
    {
        dim3 grid(DM / 128, SQ / 128, NB);
        gemm_ab_f16<<<grid, 256, smem_ab>>>(p, vh, out, DM, SQ,
                                            (long)SQ * SQ, (long)SQ * DM,
                                            (long)SQ * DM);
    }
}